// round 3
// baseline (speedup 1.0000x reference)
#include <cuda_runtime.h>
#include <math.h>

#define BB 512
#define CC 256
#define NW 8          // 256 concepts / 32 bits
#define TEMP_INV (1.0f/0.07f)

// ---- scratch (no allocation allowed) ----
__device__ float    g_clip[2*BB];   // per-row (lse - diag) for image[0..511], text[512..1023]
__device__ float    g_ccl [2*BB];   // per-row masked-bce sum [0..511], mask sum [512..1023]
__device__ float    g_kl  [BB];     // per-row KL term
__device__ unsigned g_bits[BB*NW];  // binary concept bitmasks

// ---------- deterministic block reductions (256 threads) ----------
__device__ __forceinline__ float blockSum(float v) {
    __shared__ float sh[9];
    int tid = threadIdx.x;
    #pragma unroll
    for (int o = 16; o > 0; o >>= 1) v += __shfl_down_sync(0xffffffffu, v, o);
    __syncthreads();
    if ((tid & 31) == 0) sh[tid >> 5] = v;
    __syncthreads();
    if (tid == 0) {
        float s = 0.f;
        #pragma unroll
        for (int w = 0; w < 8; w++) s += sh[w];
        sh[8] = s;
    }
    __syncthreads();
    return sh[8];
}

__device__ __forceinline__ float blockMax(float v) {
    __shared__ float sh[9];
    int tid = threadIdx.x;
    #pragma unroll
    for (int o = 16; o > 0; o >>= 1) v = fmaxf(v, __shfl_down_sync(0xffffffffu, v, o));
    __syncthreads();
    if ((tid & 31) == 0) sh[tid >> 5] = v;
    __syncthreads();
    if (tid == 0) {
        float s = sh[0];
        #pragma unroll
        for (int w = 1; w < 8; w++) s = fmaxf(s, sh[w]);
        sh[8] = s;
    }
    __syncthreads();
    return sh[8];
}

// ---------- kernel 1: CLIP per-row (lse - diag). 1024 blocks x 256 ----------
__global__ void __launch_bounds__(256) clip_kernel(const float* __restrict__ img,
                                                   const float* __restrict__ txt) {
    int idx = blockIdx.x;                 // 0..1023
    const float* base = (idx < BB) ? img : txt;
    int row = idx & (BB - 1);
    const float* r = base + (size_t)row * BB;
    int tid = threadIdx.x;

    float v0 = r[tid];
    float v1 = r[tid + 256];
    float m  = blockMax(fmaxf(v0, v1));
    float se = blockSum(__expf(v0 - m) + __expf(v1 - m));
    if (tid == 0)
        g_clip[idx] = m + logf(se) - r[row];
}

// ---------- kernel 2: BCE concept loss + bitmask build. 512 blocks x 256 ----------
__global__ void __launch_bounds__(256) concept_kernel(const float* __restrict__ cl,
                                                      const int*   __restrict__ mc) {
    int row = blockIdx.x;
    int c   = threadIdx.x;                 // one concept per thread
    int m   = mc[(size_t)row * CC + c];
    float mask = (m != -1) ? 1.f : 0.f;
    float tgt  = (m > 0)  ? 1.f : 0.f;
    float x    = cl[(size_t)row * CC + c];
    // stable logaddexp(0,x) - x*t
    float la = (x > 0.f) ? (x + log1pf(__expf(-x))) : log1pf(__expf(x));
    float loss = (la - x * tgt) * mask;

    unsigned ball = __ballot_sync(0xffffffffu, m > 0);
    if ((c & 31) == 0) g_bits[row * NW + (c >> 5)] = ball;

    float ls = blockSum(loss);
    float ms = blockSum(mask);
    if (c == 0) { g_ccl[row] = ls; g_ccl[BB + row] = ms; }
}

// ---------- kernel 3: Jaccard -> softmax targets -> KL per row. 512 blocks x 256 ----------
__global__ void __launch_bounds__(256) kl_kernel(const float* __restrict__ cis) {
    __shared__ unsigned sbits[BB * NW];   // 16 KB, whole bit table
    __shared__ float    ssim [BB];        // scaled sim row
    __shared__ float    scis [BB];        // cis row
    int row = blockIdx.x, tid = threadIdx.x;

    for (int i = tid; i < BB * NW; i += 256) sbits[i] = g_bits[i];
    for (int i = tid; i < BB; i += 256)      scis[i]  = cis[(size_t)row * BB + i];
    __syncthreads();

    unsigned a[NW];
    #pragma unroll
    for (int w = 0; w < NW; w++) a[w] = sbits[row * NW + w];

    float maxs = -3.402823e38f, maxc = -3.402823e38f;
    for (int j = tid; j < BB; j += 256) {
        const unsigned* bj = &sbits[j * NW];
        int inter = 0, uni = 0;
        #pragma unroll
        for (int w = 0; w < NW; w++) {
            unsigned b = bj[w];
            inter += __popc(a[w] & b);
            uni   += __popc(a[w] | b);
        }
        float sim = (uni > 0) ? (float)inter / (float)uni : 0.f;
        float s = sim * TEMP_INV;
        ssim[j] = s;
        maxs = fmaxf(maxs, s);
        maxc = fmaxf(maxc, scis[j]);
    }
    maxs = blockMax(maxs);
    maxc = blockMax(maxc);

    float es = 0.f, ec = 0.f, num = 0.f;
    for (int j = tid; j < BB; j += 256) {
        float s  = ssim[j];
        float ci = scis[j];
        float e  = __expf(s - maxs);
        es  += e;
        num += e * (s - ci);
        ec  += __expf(ci - maxc);
    }
    es  = blockSum(es);
    ec  = blockSum(ec);
    num = blockSum(num);
    if (tid == 0)
        // KL_i = sum_j t_j (log t_j - logp_j)
        //      = num/Zs - max_s - log Zs + (max_c + log Zc)
        g_kl[row] = num / es - maxs - logf(es) + maxc + logf(ec);
}

// ---------- kernel 4: final combine. 1 block x 256 ----------
__global__ void __launch_bounds__(256) final_kernel(float* __restrict__ out) {
    int tid = threadIdx.x;
    float cs = 0.f, ls = 0.f, ms = 0.f, ks = 0.f;
    for (int i = tid; i < 2 * BB; i += 256) cs += g_clip[i];
    for (int i = tid; i < BB; i += 256) {
        ls += g_ccl[i];
        ms += g_ccl[BB + i];
        ks += g_kl[i];
    }
    cs = blockSum(cs);
    ls = blockSum(ls);
    ms = blockSum(ms);
    ks = blockSum(ks);
    if (tid == 0) {
        float clip_loss = cs / (2.f * BB);
        float bce_loss  = ls / (ms + 1e-8f);
        float kl_loss   = ks / (float)BB;
        out[0] = clip_loss + 0.5f * bce_loss + 0.3f * kl_loss;
    }
}

extern "C" void kernel_launch(void* const* d_in, const int* in_sizes, int n_in,
                              void* d_out, int out_size) {
    const float* img = (const float*)d_in[0];   // logits_per_image [512,512]
    const float* txt = (const float*)d_in[1];   // logits_per_text  [512,512]
    const float* cl  = (const float*)d_in[2];   // concepts_logits  [512,256]
    const float* cis = (const float*)d_in[3];   // concepts_image_similarity [512,512]
    const int*   mc  = (const int*)d_in[4];     // medical_concepts [512,256]
    float* out = (float*)d_out;

    clip_kernel   <<<2 * BB, 256>>>(img, txt);
    concept_kernel<<<BB, 256>>>(cl, mc);
    kl_kernel     <<<BB, 256>>>(cis);
    final_kernel  <<<1, 256>>>(out);
}